// round 12
// baseline (speedup 1.0000x reference)
#include <cuda_runtime.h>
#include <cuda_fp16.h>
#include <math.h>

#define NN 200000
#define EE 400000
#define GG 8000
#define NSLOT 64          // bn accumulator slots
#define NBI 444           // persistent grid for csr kernel
#define CH 452            // nodes per block in csr scan (444*452 >= 200000)
#define PAD 68            // smem row pad: float4-aligned, bank-shifting

// ---------------- device scratch ----------------
__device__ float    g_h  [NN*64];
__device__ __half   g_hnh[NN*64];
__device__ float    g_as [NN*4];
__device__ float    g_ad [NN*4];
__device__ float    g_sc [EE*4];
__device__ int      g_deg[NN];
__device__ int      g_rowstart[NN+1];
__device__ int      g_cursor[NN];
__device__ int      g_esrc[EE];
__device__ int      g_epos[EE];
__device__ int      g_bsum[NBI];
__device__ float    g_bnacc[3][NSLOT][128];   // [layer][slot][sum(64) | sumsq(64)]
__device__ unsigned g_gmaxu[4];               // per-head global score max (ordered-uint)
__device__ float    g_scale[64];
__device__ float    g_shift[64];
__device__ float    g_vsrc[256];
__device__ float    g_vdst[256];
__device__ float    g_wedge[32];
__device__ int          g_bar_count = 0;
__device__ volatile int g_bar_gen   = 0;

#define FULLM 0xffffffffu

// ---------------- software grid barrier (generation counter) ----------------
__device__ __forceinline__ void grid_barrier(int nblocks) {
    __syncthreads();
    if (threadIdx.x == 0) {
        __threadfence();
        int gen = g_bar_gen;
        if (atomicAdd(&g_bar_count, 1) == nblocks - 1) {
            g_bar_count = 0;
            __threadfence();
            g_bar_gen = gen + 1;
        } else {
            while (g_bar_gen == gen) { }
        }
        __threadfence();
    }
    __syncthreads();
}

// ordered-uint encoding for float atomicMax (monotone increasing)
__device__ __forceinline__ unsigned encf(float f) {
    unsigned u = __float_as_uint(f);
    return (u & 0x80000000u) ? ~u : (u | 0x80000000u);
}
__device__ __forceinline__ float decf(unsigned u) {
    return (u & 0x80000000u) ? __uint_as_float(u & 0x7fffffffu)
                             : __uint_as_float(~u);
}

// ---------------- f32x2 packed math helpers ----------------
__device__ __forceinline__ unsigned long long pk2(float a, float b) {
    unsigned long long r;
    asm("mov.b64 %0, {%1, %2};" : "=l"(r) : "f"(a), "f"(b));
    return r;
}
__device__ __forceinline__ void fma2(unsigned long long& d,
                                     unsigned long long a, unsigned long long b) {
    asm("fma.rn.f32x2 %0, %1, %2, %0;" : "+l"(d) : "l"(a), "l"(b));
}
__device__ __forceinline__ float2 upk2(unsigned long long v) {
    float2 r;
    asm("mov.b64 {%0, %1}, %2;" : "=f"(r.x), "=f"(r.y) : "l"(v));
    return r;
}

__device__ __forceinline__ float lrelu(float a) { return a > 0.f ? a : 0.2f * a; }

// ---------------- fused CSR build: zero+degree+scan+fill (1 launch) --------
__global__ __launch_bounds__(256, 4) void k_csr(const int* __restrict__ ei) {
    __shared__ int s_w1[8];
    __shared__ int s_w2[8];
    __shared__ int s_boff;
    int tid = threadIdx.x, bid = blockIdx.x;
    int wid = tid >> 5, lane = tid & 31;

    // phase 1: zero deg + bn accumulators
    for (int i = bid * 256 + tid; i < NN; i += NBI * 256) g_deg[i] = 0;
    for (int i = bid * 256 + tid; i < 3 * NSLOT * 128; i += NBI * 256)
        ((float*)g_bnacc)[i] = 0.0f;
    grid_barrier(NBI);

    // phase 2: degree count
    for (int e = bid * 256 + tid; e < EE; e += NBI * 256)
        atomicAdd(&g_deg[ei[EE + e]], 1);
    grid_barrier(NBI);

    // phase 3: per-block degree totals
    int base = bid * CH;
    {
        int psum = 0;
        for (int j = tid; j < CH; j += 256) {
            int n = base + j;
            if (n < NN) psum += g_deg[n];
        }
        #pragma unroll
        for (int off = 16; off > 0; off >>= 1) psum += __shfl_down_sync(FULLM, psum, off);
        if (lane == 0) s_w1[wid] = psum;
        __syncthreads();
        if (tid == 0) {
            int t = 0;
            #pragma unroll
            for (int w = 0; w < 8; w++) t += s_w1[w];
            g_bsum[bid] = t;
        }
    }
    grid_barrier(NBI);

    // phase 4+5: block offset + local pair scan
    {
        int off = 0;
        for (int b = tid; b < NBI; b += 256)
            if (b < bid) off += g_bsum[b];
        #pragma unroll
        for (int o = 16; o > 0; o >>= 1) off += __shfl_down_sync(FULLM, off, o);
        if (lane == 0) s_w2[wid] = off;
        __syncthreads();
        if (tid == 0) {
            int t = 0;
            #pragma unroll
            for (int w = 0; w < 8; w++) t += s_w2[w];
            s_boff = t;
        }
        __syncthreads();
        int boff = s_boff;

        int n0 = base + 2 * tid, n1 = n0 + 1;
        int d0 = (2 * tid     < CH && n0 < NN) ? g_deg[n0] : 0;
        int d1 = (2 * tid + 1 < CH && n1 < NN) ? g_deg[n1] : 0;
        int pair = d0 + d1;
        int incl = pair;
        #pragma unroll
        for (int o = 1; o < 32; o <<= 1) {
            int v = __shfl_up_sync(FULLM, incl, o);
            if (lane >= o) incl += v;
        }
        __syncthreads();
        if (lane == 31) s_w1[wid] = incl;
        __syncthreads();
        int woff = 0;
        for (int w = 0; w < wid; w++) woff += s_w1[w];
        int excl = incl - pair + woff;
        int rs0 = boff + excl;
        int rs1 = rs0 + d0;
        if (2 * tid < CH && n0 <= NN) {
            g_rowstart[n0] = rs0;
            if (n0 < NN) g_cursor[n0] = rs0;
        }
        if (2 * tid + 1 < CH && n1 <= NN) {
            g_rowstart[n1] = rs1;
            if (n1 < NN) g_cursor[n1] = rs1;
        }
    }
    grid_barrier(NBI);

    // phase 6: fill CSR
    for (int e = bid * 256 + tid; e < EE; e += NBI * 256) {
        int d = ei[EE + e];
        int s = ei[e];
        int p = atomicAdd(&g_cursor[d], 1);
        g_esrc[p] = s;
        g_epos[e] = p;
    }
}

// ---------------- input projection (+ BN stats for layer 0) ----------------
__global__ void k_lin(const float* __restrict__ x,
                      const float* __restrict__ lin_w,
                      const float* __restrict__ lin_b) {
    __shared__ float ws[2048];
    __shared__ float xt[8 * 32];
    int c = threadIdx.x;            // 0..63
    int r = threadIdx.y;            // 0..7
    int tid = c + r * 64;           // 0..511
    for (int i = tid; i < 2048; i += 512) ws[i] = lin_w[i];
    if (tid < 256) {
        int rr = tid >> 5, kk = tid & 31;
        xt[rr * 32 + kk] = x[(blockIdx.x * 8 + rr) * 32 + kk];
    }
    __syncthreads();
    float a = lin_b[c];
    #pragma unroll
    for (int k = 0; k < 32; k++) a = fmaf(xt[r * 32 + k], ws[k * 64 + c], a);
    a = fmaxf(a, 0.0f);
    g_h[(blockIdx.x * 8 + r) * 64 + c] = a;
    __syncthreads();
    ws[r * 64 + c] = a;
    __syncthreads();
    if (r == 0) {
        float s1 = 0.f, s2 = 0.f;
        #pragma unroll
        for (int rr = 0; rr < 8; rr++) {
            float v = ws[rr * 64 + c];
            s1 += v; s2 += v * v;
        }
        int slot = blockIdx.x & (NSLOT - 1);
        atomicAdd(&g_bnacc[0][slot][c], s1);
        atomicAdd(&g_bnacc[0][slot][64 + c], s2);
    }
}

// ---------------- bn finalize + fold attention vectors + reset gmax ------
__global__ void k_bnfin(int l,
                        const float* __restrict__ gamma,
                        const float* __restrict__ beta,
                        const float* __restrict__ conv_w,
                        const float* __restrict__ conv_we,
                        const float* __restrict__ att_src,
                        const float* __restrict__ att_dst,
                        const float* __restrict__ att_edge) {
    int tid = threadIdx.x;
    if (tid < 64) {
        float s1 = 0.f, s2 = 0.f;
        for (int b = 0; b < NSLOT; b++) {
            s1 += g_bnacc[l][b][tid];
            s2 += g_bnacc[l][b][64 + tid];
        }
        float mu = s1 / (float)NN;
        float var = s2 / (float)NN - mu * mu;
        float sc = gamma[l * 64 + tid] * rsqrtf(var + 1e-5f);
        g_scale[tid] = sc;
        g_shift[tid] = beta[l * 64 + tid] - mu * sc;
    }
    if (tid < 4) g_gmaxu[tid] = encf(-1e30f);
    {
        int h = tid >> 6, k = tid & 63;
        const float* W = conv_w + l * 16384 + k * 256 + h * 64;
        const float* as = att_src + l * 256 + h * 64;
        const float* ad = att_dst + l * 256 + h * 64;
        float vs = 0.f, vd = 0.f;
        #pragma unroll 8
        for (int c = 0; c < 64; c++) { float w = W[c]; vs += w * as[c]; vd += w * ad[c]; }
        g_vsrc[tid] = vs;
        g_vdst[tid] = vd;
    }
    if (tid < 32) {
        int h = tid >> 3, j = tid & 7;
        const float* We = conv_we + l * 2048 + j * 256 + h * 64;
        const float* ae = att_edge + l * 256 + h * 64;
        float we = 0.f;
        #pragma unroll 8
        for (int c = 0; c < 64; c++) we += We[c] * ae[c];
        g_wedge[tid] = we;
    }
}

// BN apply -> hnh (fp16) + a_s/a_d via smem mini-GEMM (NO shuffles)
// 64 nodes/block, 256 threads. Padded smem rows -> conflict-free LDS.128.
__global__ __launch_bounds__(256) void k_bnapply() {
    __shared__ float hn[64 * PAD];
    __shared__ float vv[8 * PAD];      // rows 0-3: vsrc[h], rows 4-7: vdst[h]
    __shared__ float ssc[64], ssh[64];
    int tid = threadIdx.x;
    int nb = blockIdx.x * 64;

    if (tid < 64) { ssc[tid] = g_scale[tid]; ssh[tid] = g_shift[tid]; }
    for (int i = tid; i < 512; i += 256) {
        int j = i >> 6, c = i & 63;
        vv[j * PAD + c] = (j < 4) ? g_vsrc[j * 64 + c] : g_vdst[(j - 4) * 64 + c];
    }
    __syncthreads();

    // load + bn apply + fp16 store + smem stage (coalesced float4)
    #pragma unroll
    for (int i = tid * 4; i < 4096; i += 1024) {
        int node = i >> 6, c = i & 63;
        float4 hq = *(const float4*)&g_h[nb * 64 + i];
        float4 o;
        o.x = hq.x * ssc[c]     + ssh[c];
        o.y = hq.y * ssc[c + 1] + ssh[c + 1];
        o.z = hq.z * ssc[c + 2] + ssh[c + 2];
        o.w = hq.w * ssc[c + 3] + ssh[c + 3];
        __half2 h0 = __floats2half2_rn(o.x, o.y);
        __half2 h1 = __floats2half2_rn(o.z, o.w);
        *(__half2*)&g_hnh[nb * 64 + i]     = h0;
        *(__half2*)&g_hnh[nb * 64 + i + 2] = h1;
        *(float4*)&hn[node * PAD + c] = o;
    }
    __syncthreads();

    // 512 dot-products (64 nodes x 8 outputs), 2 per thread
    #pragma unroll
    for (int rep = 0; rep < 2; rep++) {
        int o = tid + rep * 256;
        int node = o >> 3, j = o & 7;
        const float* hrow = &hn[node * PAD];
        const float* vrow = &vv[j * PAD];
        float acc = 0.f;
        #pragma unroll
        for (int c4 = 0; c4 < 64; c4 += 4) {
            float4 hq = *(const float4*)&hrow[c4];
            float4 vq = *(const float4*)&vrow[c4];
            acc += hq.x * vq.x + hq.y * vq.y + hq.z * vq.z + hq.w * vq.w;
        }
        int n = nb + node;
        if (j < 4) g_as[n * 4 + j] = acc;
        else       g_ad[n * 4 + j - 4] = acc;
    }
}

// edge scores -> CSR positions + per-head global max
__global__ void k_escore(const float* __restrict__ edge_attr,
                         const int* __restrict__ ei) {
    __shared__ float we[32];
    __shared__ float red[8][4];
    int tid = threadIdx.x;
    if (tid < 32) we[tid] = g_wedge[tid];
    __syncthreads();
    int e = blockIdx.x * 256 + tid;
    float o[4] = {-1e30f, -1e30f, -1e30f, -1e30f};
    if (e < EE) {
        int sv = ei[e];
        int dv = ei[EE + e];
        float4 as4 = *(const float4*)&g_as[sv * 4];
        float4 ad4 = *(const float4*)&g_ad[dv * 4];
        float4 e0 = *(const float4*)(edge_attr + e * 8);
        float4 e1 = *(const float4*)(edge_attr + e * 8 + 4);
        float ax[4] = {as4.x + ad4.x, as4.y + ad4.y, as4.z + ad4.z, as4.w + ad4.w};
        #pragma unroll
        for (int h = 0; h < 4; h++) {
            const float* w = &we[h * 8];
            float ae = e0.x*w[0] + e0.y*w[1] + e0.z*w[2] + e0.w*w[3]
                     + e1.x*w[4] + e1.y*w[5] + e1.z*w[6] + e1.w*w[7];
            o[h] = lrelu(ax[h] + ae);
        }
        int p = g_epos[e];
        *(float4*)&g_sc[p * 4] = make_float4(o[0], o[1], o[2], o[3]);
    }
    float m[4] = {o[0], o[1], o[2], o[3]};
    #pragma unroll
    for (int off = 16; off > 0; off >>= 1) {
        #pragma unroll
        for (int h = 0; h < 4; h++)
            m[h] = fmaxf(m[h], __shfl_xor_sync(FULLM, m[h], off));
    }
    if ((tid & 31) == 0) {
        #pragma unroll
        for (int h = 0; h < 4; h++) red[tid >> 5][h] = m[h];
    }
    __syncthreads();
    if (tid < 4) {
        float mm = red[0][tid];
        #pragma unroll
        for (int wg = 1; wg < 8; wg++) mm = fmaxf(mm, red[wg][tid]);
        atomicMax(&g_gmaxu[tid], encf(mm));
    }
}

// ---------------- fused conv + GEMM + bias/relu/skip + BN stats ----------
// 256 threads, 32 nodes per block, 48KB smem, 4 blocks/SM.
__global__ __launch_bounds__(256, 4) void k_conv_gemm(
        int l,
        const float* __restrict__ conv_w,
        const float* __restrict__ conv_bias) {
    extern __shared__ float sm[];
    float* sSh = sm;             // 8192 floats (32 nodes x 256)
    float* wSh = sm + 8192;      // 4096 floats (64x64 W slice)
    int tid = threadIdx.x;
    int wid = tid >> 5, lane = tid & 31;
    int nb = blockIdx.x * 32;

    float gm0 = decf(g_gmaxu[0]);
    float gm1 = decf(g_gmaxu[1]);
    float gm2 = decf(g_gmaxu[2]);
    float gm3 = decf(g_gmaxu[3]);

    // ---------- Phase A: single-pass softmax + aggregation ----------
    for (int jj = 0; jj < 4; jj++) {
        int nloc = (wid << 2) + jj;
        int n = nb + nloc;
        int start = g_rowstart[n];
        int end   = g_rowstart[n + 1];
        float den0 = 0.f, den1 = 0.f, den2 = 0.f, den3 = 0.f;
        float aA0 = 0.f, aA1 = 0.f, aA2 = 0.f, aA3 = 0.f;
        float aB0 = 0.f, aB1 = 0.f, aB2 = 0.f, aB3 = 0.f;
        for (int i = start; i < end; i++) {
            float4 sc = *(const float4*)&g_sc[i * 4];
            int sv = g_esrc[i];
            float w0 = __expf(sc.x - gm0);
            float w1 = __expf(sc.y - gm1);
            float w2 = __expf(sc.z - gm2);
            float w3 = __expf(sc.w - gm3);
            den0 += w0; den1 += w1; den2 += w2; den3 += w3;
            __half2 hh = ((const __half2*)g_hnh)[sv * 32 + lane];
            float2 hf = __half22float2(hh);
            aA0 = fmaf(w0, hf.x, aA0); aB0 = fmaf(w0, hf.y, aB0);
            aA1 = fmaf(w1, hf.x, aA1); aB1 = fmaf(w1, hf.y, aB1);
            aA2 = fmaf(w2, hf.x, aA2); aB2 = fmaf(w2, hf.y, aB2);
            aA3 = fmaf(w3, hf.x, aA3); aB3 = fmaf(w3, hf.y, aB3);
        }
        float i0 = 1.f / (den0 + 1e-16f);
        float i1 = 1.f / (den1 + 1e-16f);
        float i2 = 1.f / (den2 + 1e-16f);
        float i3 = 1.f / (den3 + 1e-16f);
        int base = nloc * 256 + 2 * lane;
        *(float2*)&sSh[base +   0] = make_float2(aA0 * i0, aB0 * i0);
        *(float2*)&sSh[base +  64] = make_float2(aA1 * i1, aB1 * i1);
        *(float2*)&sSh[base + 128] = make_float2(aA2 * i2, aB2 * i2);
        *(float2*)&sSh[base + 192] = make_float2(aA3 * i3, aB3 * i3);
    }

    // ---------- Phase B: projection GEMM (f32x2, 4n x 2c per thread) ------
    int cg = tid & 31;            // 32 channel groups x 2 channels
    int ng = tid >> 5;            // 8 node groups x 4 nodes (warp-uniform)
    int c0 = cg * 2;
    unsigned long long acc[4];
    #pragma unroll
    for (int j = 0; j < 4; j++) acc[j] = 0ULL;

    const float* Wg = conv_w + l * 16384;
    for (int h = 0; h < 4; h++) {
        __syncthreads();
        for (int i = tid; i < 1024; i += 256) {
            int row = i >> 4, c4 = (i & 15) * 4;
            *(float4*)&wSh[row * 64 + c4] = *(const float4*)&Wg[row * 256 + h * 64 + c4];
        }
        __syncthreads();
        const float* sp = sSh + h * 64;
        #pragma unroll 4
        for (int k4 = 0; k4 < 16; k4++) {
            float4 s0 = *(const float4*)&sp[(ng * 4 + 0) * 256 + k4 * 4];
            float4 s1 = *(const float4*)&sp[(ng * 4 + 1) * 256 + k4 * 4];
            float4 s2 = *(const float4*)&sp[(ng * 4 + 2) * 256 + k4 * 4];
            float4 s3 = *(const float4*)&sp[(ng * 4 + 3) * 256 + k4 * 4];
            #pragma unroll
            for (int kk = 0; kk < 4; kk++) {
                float2 w = *(const float2*)&wSh[(k4 * 4 + kk) * 64 + c0];
                unsigned long long wp = pk2(w.x, w.y);
                float f0 = (kk == 0) ? s0.x : (kk == 1) ? s0.y : (kk == 2) ? s0.z : s0.w;
                float f1 = (kk == 0) ? s1.x : (kk == 1) ? s1.y : (kk == 2) ? s1.z : s1.w;
                float f2 = (kk == 0) ? s2.x : (kk == 1) ? s2.y : (kk == 2) ? s2.z : s2.w;
                float f3 = (kk == 0) ? s3.x : (kk == 1) ? s3.y : (kk == 2) ? s3.z : s3.w;
                fma2(acc[0], pk2(f0, f0), wp);
                fma2(acc[1], pk2(f1, f1), wp);
                fma2(acc[2], pk2(f2, f2), wp);
                fma2(acc[3], pk2(f3, f3), wp);
            }
        }
    }

    // epilogue: mean over heads, bias, relu, skip; collect BN stats
    float2 bias2 = *(const float2*)&conv_bias[l * 64 + c0];
    float bsx1 = 0.f, bsy1 = 0.f, bsx2 = 0.f, bsy2 = 0.f;
    #pragma unroll
    for (int j = 0; j < 4; j++) {
        int node = nb + ng * 4 + j;
        float2 v = upk2(acc[j]);
        float2 old = *(const float2*)&g_h[node * 64 + c0];
        float2 o;
        o.x = fmaxf(v.x * 0.25f + bias2.x, 0.0f) + old.x;
        o.y = fmaxf(v.y * 0.25f + bias2.y, 0.0f) + old.y;
        *(float2*)&g_h[node * 64 + c0] = o;
        bsx1 += o.x; bsy1 += o.y;
        bsx2 += o.x * o.x; bsy2 += o.y * o.y;
    }
    if (l < 2) {
        __syncthreads();
        *(float2*)&sSh[ng * 128 + c0]      = make_float2(bsx1, bsy1);
        *(float2*)&sSh[ng * 128 + 64 + c0] = make_float2(bsx2, bsy2);
        __syncthreads();
        if (tid < 128) {
            float acc2 = 0.f;
            #pragma unroll
            for (int q = 0; q < 8; q++) acc2 += sSh[q * 128 + tid];
            atomicAdd(&g_bnacc[l + 1][blockIdx.x & (NSLOT - 1)][tid], acc2);
        }
    }
}

// ---------------- pooling + MLP head (fused, deterministic) ----------------
__device__ __forceinline__ int lower_bound_dev(const int* b, int n, int v) {
    int lo = 0, hi = n;
    while (lo < hi) {
        int mid = (lo + hi) >> 1;
        if (b[mid] < v) lo = mid + 1; else hi = mid;
    }
    return lo;
}

__global__ void k_pool_mlp(const int* __restrict__ batch,
                           const float* __restrict__ fc1_w,
                           const float* __restrict__ fc1_b,
                           const float* __restrict__ fc2_w,
                           const float* __restrict__ fc2_b,
                           float* __restrict__ out) {
    __shared__ float ps[64];
    __shared__ float r2[2];
    int g = blockIdx.x;
    int tid = threadIdx.x;
    int start = lower_bound_dev(batch, NN, g);
    int end   = lower_bound_dev(batch, NN, g + 1);
    float s = 0.f;
    for (int n = start; n < end; n++) s += g_h[n * 64 + tid];
    ps[tid] = s;
    __syncthreads();
    float z = fc1_b[tid];
    #pragma unroll 8
    for (int k = 0; k < 64; k++) z = fmaf(ps[k], fc1_w[k * 64 + tid], z);
    z = fmaxf(z, 0.0f);
    float p = z * fc2_w[tid];
    #pragma unroll
    for (int off = 16; off > 0; off >>= 1) p += __shfl_down_sync(FULLM, p, off);
    if ((tid & 31) == 0) r2[tid >> 5] = p;
    __syncthreads();
    if (tid == 0) out[g] = fmaxf(r2[0] + r2[1] + fc2_b[0], 0.0f);
}

// ---------------- launcher ----------------
extern "C" void kernel_launch(void* const* d_in, const int* in_sizes, int n_in,
                              void* d_out, int out_size) {
    const float* x         = (const float*)d_in[0];
    const int*   ei        = (const int*)  d_in[1];
    const float* edge_attr = (const float*)d_in[2];
    const int*   batch     = (const int*)  d_in[3];
    const float* lin_w     = (const float*)d_in[4];
    const float* lin_b     = (const float*)d_in[5];
    const float* bn_gamma  = (const float*)d_in[6];
    const float* bn_beta   = (const float*)d_in[7];
    const float* conv_w    = (const float*)d_in[8];
    const float* conv_we   = (const float*)d_in[9];
    const float* att_src   = (const float*)d_in[10];
    const float* att_dst   = (const float*)d_in[11];
    const float* att_edge  = (const float*)d_in[12];
    const float* conv_bias = (const float*)d_in[13];
    const float* fc1_w     = (const float*)d_in[14];
    const float* fc1_b     = (const float*)d_in[15];
    const float* fc2_w     = (const float*)d_in[16];
    const float* fc2_b     = (const float*)d_in[17];
    float* out = (float*)d_out;

    const int smem_cg = (8192 + 4096) * 4;   // 49152 B
    cudaFuncSetAttribute(k_conv_gemm, cudaFuncAttributeMaxDynamicSharedMemorySize, smem_cg);

    // launch 0: fused CSR build
    k_csr<<<NBI, 256>>>(ei);
    // launch 1: input projection (+ layer-0 BN stats)
    k_lin<<<NN / 8, dim3(64, 8)>>>(x, lin_w, lin_b);

    for (int l = 0; l < 3; l++) {
        k_bnfin<<<1, 256>>>(l, bn_gamma, bn_beta, conv_w, conv_we,
                            att_src, att_dst, att_edge);
        k_bnapply<<<NN / 64, 256>>>();
        k_escore<<<(EE + 255) / 256, 256>>>(edge_attr, ei);
        k_conv_gemm<<<NN / 32, 256, smem_cg>>>(l, conv_w, conv_bias);
    }

    k_pool_mlp<<<GG, 64>>>(batch, fc1_w, fc1_b, fc2_w, fc2_b, out);
}

// round 14
// speedup vs baseline: 1.5573x; 1.5573x over previous
#include <cuda_runtime.h>
#include <cuda_fp16.h>
#include <math.h>

#define NN 200000
#define EE 400000
#define GG 8000
#define NSLOT 64          // bn accumulator slots
#define NBI 444           // persistent grid for csr kernel
#define CH 452            // nodes per block in csr scan (444*452 >= 200000)
#define PAD 68            // smem row pad: float4-aligned, bank-shifting

// ---------------- device scratch ----------------
__device__ float    g_h  [NN*64];
__device__ __half   g_hnh[NN*64];
__device__ float    g_as [NN*4];
__device__ float    g_ad [NN*4];
__device__ float    g_sc [EE*4];
__device__ int      g_deg[NN];
__device__ int      g_rowstart[NN+1];
__device__ int      g_cursor[NN];
__device__ int      g_esrc[EE];
__device__ int      g_epos[EE];
__device__ int      g_bsum[NBI];
__device__ float    g_bnacc[3][NSLOT][128];   // [layer][slot][sum(64) | sumsq(64)]
__device__ unsigned g_gmaxu[4];               // per-head global score max (ordered-uint)
__device__ float    g_scale[64];
__device__ float    g_shift[64];
__device__ float    g_vsrc[256];
__device__ float    g_vdst[256];
__device__ float    g_wedge[32];
__device__ int          g_bar_count = 0;
__device__ volatile int g_bar_gen   = 0;

#define FULLM 0xffffffffu

// ---------------- software grid barrier (generation counter) ----------------
__device__ __forceinline__ void grid_barrier(int nblocks) {
    __syncthreads();
    if (threadIdx.x == 0) {
        __threadfence();
        int gen = g_bar_gen;
        if (atomicAdd(&g_bar_count, 1) == nblocks - 1) {
            g_bar_count = 0;
            __threadfence();
            g_bar_gen = gen + 1;
        } else {
            while (g_bar_gen == gen) { }
        }
        __threadfence();
    }
    __syncthreads();
}

// ordered-uint encoding for float atomicMax (monotone increasing)
__device__ __forceinline__ unsigned encf(float f) {
    unsigned u = __float_as_uint(f);
    return (u & 0x80000000u) ? ~u : (u | 0x80000000u);
}
__device__ __forceinline__ float decf(unsigned u) {
    return (u & 0x80000000u) ? __uint_as_float(u & 0x7fffffffu)
                             : __uint_as_float(~u);
}

// ---------------- f32x2 packed math helpers ----------------
__device__ __forceinline__ unsigned long long pk2(float a, float b) {
    unsigned long long r;
    asm("mov.b64 %0, {%1, %2};" : "=l"(r) : "f"(a), "f"(b));
    return r;
}
__device__ __forceinline__ void fma2(unsigned long long& d,
                                     unsigned long long a, unsigned long long b) {
    asm("fma.rn.f32x2 %0, %1, %2, %0;" : "+l"(d) : "l"(a), "l"(b));
}
__device__ __forceinline__ float2 upk2(unsigned long long v) {
    float2 r;
    asm("mov.b64 {%0, %1}, %2;" : "=f"(r.x), "=f"(r.y) : "l"(v));
    return r;
}

__device__ __forceinline__ float lrelu(float a) { return a > 0.f ? a : 0.2f * a; }

// ---------------- fused CSR build: zero+degree+scan+fill (1 launch) --------
__global__ __launch_bounds__(256, 4) void k_csr(const int* __restrict__ ei) {
    __shared__ int s_w1[8];
    __shared__ int s_w2[8];
    __shared__ int s_boff;
    int tid = threadIdx.x, bid = blockIdx.x;
    int wid = tid >> 5, lane = tid & 31;

    // phase 1: zero deg + bn accumulators
    for (int i = bid * 256 + tid; i < NN; i += NBI * 256) g_deg[i] = 0;
    for (int i = bid * 256 + tid; i < 3 * NSLOT * 128; i += NBI * 256)
        ((float*)g_bnacc)[i] = 0.0f;
    grid_barrier(NBI);

    // phase 2: degree count
    for (int e = bid * 256 + tid; e < EE; e += NBI * 256)
        atomicAdd(&g_deg[ei[EE + e]], 1);
    grid_barrier(NBI);

    // phase 3: per-block degree totals
    int base = bid * CH;
    {
        int psum = 0;
        for (int j = tid; j < CH; j += 256) {
            int n = base + j;
            if (n < NN) psum += g_deg[n];
        }
        #pragma unroll
        for (int off = 16; off > 0; off >>= 1) psum += __shfl_down_sync(FULLM, psum, off);
        if (lane == 0) s_w1[wid] = psum;
        __syncthreads();
        if (tid == 0) {
            int t = 0;
            #pragma unroll
            for (int w = 0; w < 8; w++) t += s_w1[w];
            g_bsum[bid] = t;
        }
    }
    grid_barrier(NBI);

    // phase 4+5: block offset + local pair scan
    {
        int off = 0;
        for (int b = tid; b < NBI; b += 256)
            if (b < bid) off += g_bsum[b];
        #pragma unroll
        for (int o = 16; o > 0; o >>= 1) off += __shfl_down_sync(FULLM, off, o);
        if (lane == 0) s_w2[wid] = off;
        __syncthreads();
        if (tid == 0) {
            int t = 0;
            #pragma unroll
            for (int w = 0; w < 8; w++) t += s_w2[w];
            s_boff = t;
        }
        __syncthreads();
        int boff = s_boff;

        int n0 = base + 2 * tid, n1 = n0 + 1;
        int d0 = (2 * tid     < CH && n0 < NN) ? g_deg[n0] : 0;
        int d1 = (2 * tid + 1 < CH && n1 < NN) ? g_deg[n1] : 0;
        int pair = d0 + d1;
        int incl = pair;
        #pragma unroll
        for (int o = 1; o < 32; o <<= 1) {
            int v = __shfl_up_sync(FULLM, incl, o);
            if (lane >= o) incl += v;
        }
        __syncthreads();
        if (lane == 31) s_w1[wid] = incl;
        __syncthreads();
        int woff = 0;
        for (int w = 0; w < wid; w++) woff += s_w1[w];
        int excl = incl - pair + woff;
        int rs0 = boff + excl;
        int rs1 = rs0 + d0;
        if (2 * tid < CH && n0 <= NN) {
            g_rowstart[n0] = rs0;
            if (n0 < NN) g_cursor[n0] = rs0;
        }
        if (2 * tid + 1 < CH && n1 <= NN) {
            g_rowstart[n1] = rs1;
            if (n1 < NN) g_cursor[n1] = rs1;
        }
    }
    grid_barrier(NBI);

    // phase 6: fill CSR
    for (int e = bid * 256 + tid; e < EE; e += NBI * 256) {
        int d = ei[EE + e];
        int s = ei[e];
        int p = atomicAdd(&g_cursor[d], 1);
        g_esrc[p] = s;
        g_epos[e] = p;
    }
}

// ---------------- input projection (+ BN stats for layer 0) ----------------
__global__ void k_lin(const float* __restrict__ x,
                      const float* __restrict__ lin_w,
                      const float* __restrict__ lin_b) {
    __shared__ float ws[2048];
    __shared__ float xt[8 * 32];
    int c = threadIdx.x;            // 0..63
    int r = threadIdx.y;            // 0..7
    int tid = c + r * 64;           // 0..511
    for (int i = tid; i < 2048; i += 512) ws[i] = lin_w[i];
    if (tid < 256) {
        int rr = tid >> 5, kk = tid & 31;
        xt[rr * 32 + kk] = x[(blockIdx.x * 8 + rr) * 32 + kk];
    }
    __syncthreads();
    float a = lin_b[c];
    #pragma unroll
    for (int k = 0; k < 32; k++) a = fmaf(xt[r * 32 + k], ws[k * 64 + c], a);
    a = fmaxf(a, 0.0f);
    g_h[(blockIdx.x * 8 + r) * 64 + c] = a;
    __syncthreads();
    ws[r * 64 + c] = a;
    __syncthreads();
    if (r == 0) {
        float s1 = 0.f, s2 = 0.f;
        #pragma unroll
        for (int rr = 0; rr < 8; rr++) {
            float v = ws[rr * 64 + c];
            s1 += v; s2 += v * v;
        }
        int slot = blockIdx.x & (NSLOT - 1);
        atomicAdd(&g_bnacc[0][slot][c], s1);
        atomicAdd(&g_bnacc[0][slot][64 + c], s2);
    }
}

// ---------------- bn finalize + fold attention vectors + reset gmax ------
__global__ void k_bnfin(int l,
                        const float* __restrict__ gamma,
                        const float* __restrict__ beta,
                        const float* __restrict__ conv_w,
                        const float* __restrict__ conv_we,
                        const float* __restrict__ att_src,
                        const float* __restrict__ att_dst,
                        const float* __restrict__ att_edge) {
    int tid = threadIdx.x;
    if (tid < 64) {
        float s1 = 0.f, s2 = 0.f;
        for (int b = 0; b < NSLOT; b++) {
            s1 += g_bnacc[l][b][tid];
            s2 += g_bnacc[l][b][64 + tid];
        }
        float mu = s1 / (float)NN;
        float var = s2 / (float)NN - mu * mu;
        float sc = gamma[l * 64 + tid] * rsqrtf(var + 1e-5f);
        g_scale[tid] = sc;
        g_shift[tid] = beta[l * 64 + tid] - mu * sc;
    }
    if (tid < 4) g_gmaxu[tid] = encf(-1e30f);
    {
        int h = tid >> 6, k = tid & 63;
        const float* W = conv_w + l * 16384 + k * 256 + h * 64;
        const float* as = att_src + l * 256 + h * 64;
        const float* ad = att_dst + l * 256 + h * 64;
        float vs = 0.f, vd = 0.f;
        #pragma unroll 8
        for (int c = 0; c < 64; c++) { float w = W[c]; vs += w * as[c]; vd += w * ad[c]; }
        g_vsrc[tid] = vs;
        g_vdst[tid] = vd;
    }
    if (tid < 32) {
        int h = tid >> 3, j = tid & 7;
        const float* We = conv_we + l * 2048 + j * 256 + h * 64;
        const float* ae = att_edge + l * 256 + h * 64;
        float we = 0.f;
        #pragma unroll 8
        for (int c = 0; c < 64; c++) we += We[c] * ae[c];
        g_wedge[tid] = we;
    }
}

// BN apply -> hnh (fp16) + a_s/a_d via smem mini-GEMM (NO shuffles)
// 64 nodes/block, 256 threads. Controlled unroll keeps regs low.
__global__ __launch_bounds__(256, 4) void k_bnapply() {
    __shared__ float hn[64 * PAD];
    __shared__ float vv[8 * PAD];      // rows 0-3: vsrc[h], rows 4-7: vdst[h]
    __shared__ float ssc[64], ssh[64];
    int tid = threadIdx.x;
    int nb = blockIdx.x * 64;

    if (tid < 64) { ssc[tid] = g_scale[tid]; ssh[tid] = g_shift[tid]; }
    for (int i = tid; i < 512; i += 256) {
        int j = i >> 6, c = i & 63;
        vv[j * PAD + c] = (j < 4) ? g_vsrc[j * 64 + c] : g_vdst[(j - 4) * 64 + c];
    }
    __syncthreads();

    // load + bn apply + fp16 store + smem stage (coalesced float4)
    #pragma unroll 1
    for (int i = tid * 4; i < 4096; i += 1024) {
        int node = i >> 6, c = i & 63;
        float4 hq = *(const float4*)&g_h[nb * 64 + i];
        float4 o;
        o.x = hq.x * ssc[c]     + ssh[c];
        o.y = hq.y * ssc[c + 1] + ssh[c + 1];
        o.z = hq.z * ssc[c + 2] + ssh[c + 2];
        o.w = hq.w * ssc[c + 3] + ssh[c + 3];
        __half2 h0 = __floats2half2_rn(o.x, o.y);
        __half2 h1 = __floats2half2_rn(o.z, o.w);
        *(__half2*)&g_hnh[nb * 64 + i]     = h0;
        *(__half2*)&g_hnh[nb * 64 + i + 2] = h1;
        *(float4*)&hn[node * PAD + c] = o;
    }
    __syncthreads();

    // 512 dot-products (64 nodes x 8 outputs), 2 per thread
    #pragma unroll 1
    for (int rep = 0; rep < 2; rep++) {
        int o = tid + rep * 256;
        int node = o >> 3, j = o & 7;
        const float* hrow = &hn[node * PAD];
        const float* vrow = &vv[j * PAD];
        float acc = 0.f;
        #pragma unroll 8
        for (int c4 = 0; c4 < 64; c4 += 4) {
            float4 hq = *(const float4*)&hrow[c4];
            float4 vq = *(const float4*)&vrow[c4];
            acc += hq.x * vq.x + hq.y * vq.y + hq.z * vq.z + hq.w * vq.w;
        }
        int n = nb + node;
        if (j < 4) g_as[n * 4 + j] = acc;
        else       g_ad[n * 4 + j - 4] = acc;
    }
}

// edge scores -> CSR positions + per-head global max
__global__ void k_escore(const float* __restrict__ edge_attr,
                         const int* __restrict__ ei) {
    __shared__ float we[32];
    __shared__ float red[8][4];
    int tid = threadIdx.x;
    if (tid < 32) we[tid] = g_wedge[tid];
    __syncthreads();
    int e = blockIdx.x * 256 + tid;
    float o[4] = {-1e30f, -1e30f, -1e30f, -1e30f};
    if (e < EE) {
        int sv = ei[e];
        int dv = ei[EE + e];
        float4 as4 = *(const float4*)&g_as[sv * 4];
        float4 ad4 = *(const float4*)&g_ad[dv * 4];
        float4 e0 = *(const float4*)(edge_attr + e * 8);
        float4 e1 = *(const float4*)(edge_attr + e * 8 + 4);
        float ax[4] = {as4.x + ad4.x, as4.y + ad4.y, as4.z + ad4.z, as4.w + ad4.w};
        #pragma unroll
        for (int h = 0; h < 4; h++) {
            const float* w = &we[h * 8];
            float ae = e0.x*w[0] + e0.y*w[1] + e0.z*w[2] + e0.w*w[3]
                     + e1.x*w[4] + e1.y*w[5] + e1.z*w[6] + e1.w*w[7];
            o[h] = lrelu(ax[h] + ae);
        }
        int p = g_epos[e];
        *(float4*)&g_sc[p * 4] = make_float4(o[0], o[1], o[2], o[3]);
    }
    float m[4] = {o[0], o[1], o[2], o[3]};
    #pragma unroll
    for (int off = 16; off > 0; off >>= 1) {
        #pragma unroll
        for (int h = 0; h < 4; h++)
            m[h] = fmaxf(m[h], __shfl_xor_sync(FULLM, m[h], off));
    }
    if ((tid & 31) == 0) {
        #pragma unroll
        for (int h = 0; h < 4; h++) red[tid >> 5][h] = m[h];
    }
    __syncthreads();
    if (tid < 4) {
        float mm = red[0][tid];
        #pragma unroll
        for (int wg = 1; wg < 8; wg++) mm = fmaxf(mm, red[wg][tid]);
        atomicMax(&g_gmaxu[tid], encf(mm));
    }
}

// ---------------- fused conv + GEMM + bias/relu/skip + BN stats ----------
// 256 threads, 32 nodes per block, 48KB smem, 4 blocks/SM.
__global__ __launch_bounds__(256, 4) void k_conv_gemm(
        int l,
        const float* __restrict__ conv_w,
        const float* __restrict__ conv_bias) {
    extern __shared__ float sm[];
    float* sSh = sm;             // 8192 floats (32 nodes x 256)
    float* wSh = sm + 8192;      // 4096 floats (64x64 W slice)
    int tid = threadIdx.x;
    int wid = tid >> 5, lane = tid & 31;
    int nb = blockIdx.x * 32;

    float gm0 = decf(g_gmaxu[0]);
    float gm1 = decf(g_gmaxu[1]);
    float gm2 = decf(g_gmaxu[2]);
    float gm3 = decf(g_gmaxu[3]);

    // ---------- Phase A: single-pass softmax + aggregation ----------
    for (int jj = 0; jj < 4; jj++) {
        int nloc = (wid << 2) + jj;
        int n = nb + nloc;
        int start = g_rowstart[n];
        int end   = g_rowstart[n + 1];
        float den0 = 0.f, den1 = 0.f, den2 = 0.f, den3 = 0.f;
        float aA0 = 0.f, aA1 = 0.f, aA2 = 0.f, aA3 = 0.f;
        float aB0 = 0.f, aB1 = 0.f, aB2 = 0.f, aB3 = 0.f;
        for (int i = start; i < end; i++) {
            float4 sc = *(const float4*)&g_sc[i * 4];
            int sv = g_esrc[i];
            float w0 = __expf(sc.x - gm0);
            float w1 = __expf(sc.y - gm1);
            float w2 = __expf(sc.z - gm2);
            float w3 = __expf(sc.w - gm3);
            den0 += w0; den1 += w1; den2 += w2; den3 += w3;
            __half2 hh = ((const __half2*)g_hnh)[sv * 32 + lane];
            float2 hf = __half22float2(hh);
            aA0 = fmaf(w0, hf.x, aA0); aB0 = fmaf(w0, hf.y, aB0);
            aA1 = fmaf(w1, hf.x, aA1); aB1 = fmaf(w1, hf.y, aB1);
            aA2 = fmaf(w2, hf.x, aA2); aB2 = fmaf(w2, hf.y, aB2);
            aA3 = fmaf(w3, hf.x, aA3); aB3 = fmaf(w3, hf.y, aB3);
        }
        float i0 = 1.f / (den0 + 1e-16f);
        float i1 = 1.f / (den1 + 1e-16f);
        float i2 = 1.f / (den2 + 1e-16f);
        float i3 = 1.f / (den3 + 1e-16f);
        int base = nloc * 256 + 2 * lane;
        *(float2*)&sSh[base +   0] = make_float2(aA0 * i0, aB0 * i0);
        *(float2*)&sSh[base +  64] = make_float2(aA1 * i1, aB1 * i1);
        *(float2*)&sSh[base + 128] = make_float2(aA2 * i2, aB2 * i2);
        *(float2*)&sSh[base + 192] = make_float2(aA3 * i3, aB3 * i3);
    }

    // ---------- Phase B: projection GEMM (f32x2, 4n x 2c per thread) ------
    int cg = tid & 31;            // 32 channel groups x 2 channels
    int ng = tid >> 5;            // 8 node groups x 4 nodes (warp-uniform)
    int c0 = cg * 2;
    unsigned long long acc[4];
    #pragma unroll
    for (int j = 0; j < 4; j++) acc[j] = 0ULL;

    const float* Wg = conv_w + l * 16384;
    for (int h = 0; h < 4; h++) {
        __syncthreads();
        for (int i = tid; i < 1024; i += 256) {
            int row = i >> 4, c4 = (i & 15) * 4;
            *(float4*)&wSh[row * 64 + c4] = *(const float4*)&Wg[row * 256 + h * 64 + c4];
        }
        __syncthreads();
        const float* sp = sSh + h * 64;
        #pragma unroll 4
        for (int k4 = 0; k4 < 16; k4++) {
            float4 s0 = *(const float4*)&sp[(ng * 4 + 0) * 256 + k4 * 4];
            float4 s1 = *(const float4*)&sp[(ng * 4 + 1) * 256 + k4 * 4];
            float4 s2 = *(const float4*)&sp[(ng * 4 + 2) * 256 + k4 * 4];
            float4 s3 = *(const float4*)&sp[(ng * 4 + 3) * 256 + k4 * 4];
            #pragma unroll
            for (int kk = 0; kk < 4; kk++) {
                float2 w = *(const float2*)&wSh[(k4 * 4 + kk) * 64 + c0];
                unsigned long long wp = pk2(w.x, w.y);
                float f0 = (kk == 0) ? s0.x : (kk == 1) ? s0.y : (kk == 2) ? s0.z : s0.w;
                float f1 = (kk == 0) ? s1.x : (kk == 1) ? s1.y : (kk == 2) ? s1.z : s1.w;
                float f2 = (kk == 0) ? s2.x : (kk == 1) ? s2.y : (kk == 2) ? s2.z : s2.w;
                float f3 = (kk == 0) ? s3.x : (kk == 1) ? s3.y : (kk == 2) ? s3.z : s3.w;
                fma2(acc[0], pk2(f0, f0), wp);
                fma2(acc[1], pk2(f1, f1), wp);
                fma2(acc[2], pk2(f2, f2), wp);
                fma2(acc[3], pk2(f3, f3), wp);
            }
        }
    }

    // epilogue: mean over heads, bias, relu, skip; collect BN stats
    float2 bias2 = *(const float2*)&conv_bias[l * 64 + c0];
    float bsx1 = 0.f, bsy1 = 0.f, bsx2 = 0.f, bsy2 = 0.f;
    #pragma unroll
    for (int j = 0; j < 4; j++) {
        int node = nb + ng * 4 + j;
        float2 v = upk2(acc[j]);
        float2 old = *(const float2*)&g_h[node * 64 + c0];
        float2 o;
        o.x = fmaxf(v.x * 0.25f + bias2.x, 0.0f) + old.x;
        o.y = fmaxf(v.y * 0.25f + bias2.y, 0.0f) + old.y;
        *(float2*)&g_h[node * 64 + c0] = o;
        bsx1 += o.x; bsy1 += o.y;
        bsx2 += o.x * o.x; bsy2 += o.y * o.y;
    }
    if (l < 2) {
        __syncthreads();
        *(float2*)&sSh[ng * 128 + c0]      = make_float2(bsx1, bsy1);
        *(float2*)&sSh[ng * 128 + 64 + c0] = make_float2(bsx2, bsy2);
        __syncthreads();
        if (tid < 128) {
            float acc2 = 0.f;
            #pragma unroll
            for (int q = 0; q < 8; q++) acc2 += sSh[q * 128 + tid];
            atomicAdd(&g_bnacc[l + 1][blockIdx.x & (NSLOT - 1)][tid], acc2);
        }
    }
}

// ---------------- pooling + MLP head (fused, deterministic) ----------------
__device__ __forceinline__ int lower_bound_dev(const int* b, int n, int v) {
    int lo = 0, hi = n;
    while (lo < hi) {
        int mid = (lo + hi) >> 1;
        if (b[mid] < v) lo = mid + 1; else hi = mid;
    }
    return lo;
}

__global__ void k_pool_mlp(const int* __restrict__ batch,
                           const float* __restrict__ fc1_w,
                           const float* __restrict__ fc1_b,
                           const float* __restrict__ fc2_w,
                           const float* __restrict__ fc2_b,
                           float* __restrict__ out) {
    __shared__ float ps[64];
    __shared__ float r2[2];
    int g = blockIdx.x;
    int tid = threadIdx.x;
    int start = lower_bound_dev(batch, NN, g);
    int end   = lower_bound_dev(batch, NN, g + 1);
    float s = 0.f;
    for (int n = start; n < end; n++) s += g_h[n * 64 + tid];
    ps[tid] = s;
    __syncthreads();
    float z = fc1_b[tid];
    #pragma unroll 8
    for (int k = 0; k < 64; k++) z = fmaf(ps[k], fc1_w[k * 64 + tid], z);
    z = fmaxf(z, 0.0f);
    float p = z * fc2_w[tid];
    #pragma unroll
    for (int off = 16; off > 0; off >>= 1) p += __shfl_down_sync(FULLM, p, off);
    if ((tid & 31) == 0) r2[tid >> 5] = p;
    __syncthreads();
    if (tid == 0) out[g] = fmaxf(r2[0] + r2[1] + fc2_b[0], 0.0f);
}

// ---------------- launcher ----------------
extern "C" void kernel_launch(void* const* d_in, const int* in_sizes, int n_in,
                              void* d_out, int out_size) {
    const float* x         = (const float*)d_in[0];
    const int*   ei        = (const int*)  d_in[1];
    const float* edge_attr = (const float*)d_in[2];
    const int*   batch     = (const int*)  d_in[3];
    const float* lin_w     = (const float*)d_in[4];
    const float* lin_b     = (const float*)d_in[5];
    const float* bn_gamma  = (const float*)d_in[6];
    const float* bn_beta   = (const float*)d_in[7];
    const float* conv_w    = (const float*)d_in[8];
    const float* conv_we   = (const float*)d_in[9];
    const float* att_src   = (const float*)d_in[10];
    const float* att_dst   = (const float*)d_in[11];
    const float* att_edge  = (const float*)d_in[12];
    const float* conv_bias = (const float*)d_in[13];
    const float* fc1_w     = (const float*)d_in[14];
    const float* fc1_b     = (const float*)d_in[15];
    const float* fc2_w     = (const float*)d_in[16];
    const float* fc2_b     = (const float*)d_in[17];
    float* out = (float*)d_out;

    const int smem_cg = (8192 + 4096) * 4;   // 49152 B
    cudaFuncSetAttribute(k_conv_gemm, cudaFuncAttributeMaxDynamicSharedMemorySize, smem_cg);

    // launch 0: fused CSR build
    k_csr<<<NBI, 256>>>(ei);
    // launch 1: input projection (+ layer-0 BN stats)
    k_lin<<<NN / 8, dim3(64, 8)>>>(x, lin_w, lin_b);

    for (int l = 0; l < 3; l++) {
        k_bnfin<<<1, 256>>>(l, bn_gamma, bn_beta, conv_w, conv_we,
                            att_src, att_dst, att_edge);
        k_bnapply<<<NN / 64, 256>>>();
        k_escore<<<(EE + 255) / 256, 256>>>(edge_attr, ei);
        k_conv_gemm<<<NN / 32, 256, smem_cg>>>(l, conv_w, conv_bias);
    }

    k_pool_mlp<<<GG, 64>>>(batch, fc1_w, fc1_b, fc2_w, fc2_b, out);
}

// round 16
// speedup vs baseline: 1.9673x; 1.2632x over previous
#include <cuda_runtime.h>
#include <cuda_fp16.h>
#include <math.h>

#define NN 200000
#define EE 400000
#define GG 8000
#define NSLOT 64          // bn accumulator slots
#define NBI 444           // persistent grid for csr kernel
#define CH 452            // nodes per block in csr scan (444*452 >= 200000)
#define PAD 68            // smem row pad for bnapply
#define SPADH 264         // conv smem half-stride (528B rows, 16B aligned)
#define SMEM_CONV (32*SPADH*2 + 64*SPADH*2)   // 50688 B

// ---------------- device scratch ----------------
__device__ float    g_h  [NN*64];
__device__ __half   g_hnh[NN*64];
__device__ float    g_as [NN*4];
__device__ float    g_ad [NN*4];
__device__ float    g_sc [EE*4];
__device__ int      g_deg[NN];
__device__ int      g_rowstart[NN+1];
__device__ int      g_cursor[NN];
__device__ int      g_esrc[EE];
__device__ int      g_epos[EE];
__device__ int      g_bsum[NBI];
__device__ float    g_bnacc[3][NSLOT][128];
__device__ unsigned g_gmaxu[4];
__device__ float    g_scale[64];
__device__ float    g_shift[64];
__device__ float    g_vsrc[256];
__device__ float    g_vdst[256];
__device__ float    g_wedge[32];
__device__ int          g_bar_count = 0;
__device__ volatile int g_bar_gen   = 0;

#define FULLM 0xffffffffu

// ---------------- software grid barrier ----------------
__device__ __forceinline__ void grid_barrier(int nblocks) {
    __syncthreads();
    if (threadIdx.x == 0) {
        __threadfence();
        int gen = g_bar_gen;
        if (atomicAdd(&g_bar_count, 1) == nblocks - 1) {
            g_bar_count = 0;
            __threadfence();
            g_bar_gen = gen + 1;
        } else {
            while (g_bar_gen == gen) { }
        }
        __threadfence();
    }
    __syncthreads();
}

__device__ __forceinline__ unsigned encf(float f) {
    unsigned u = __float_as_uint(f);
    return (u & 0x80000000u) ? ~u : (u | 0x80000000u);
}
__device__ __forceinline__ float decf(unsigned u) {
    return (u & 0x80000000u) ? __uint_as_float(u & 0x7fffffffu)
                             : __uint_as_float(~u);
}

__device__ __forceinline__ float lrelu(float a) { return a > 0.f ? a : 0.2f * a; }

__device__ __forceinline__ unsigned smem_u32(const void* p) {
    unsigned a;
    asm("{ .reg .u64 t; cvta.to.shared.u64 t, %1; cvt.u32.u64 %0, t; }"
        : "=r"(a) : "l"(p));
    return a;
}

// ---------------- fused CSR build ----------------
__global__ __launch_bounds__(256, 4) void k_csr(const int* __restrict__ ei) {
    __shared__ int s_w1[8];
    __shared__ int s_w2[8];
    __shared__ int s_boff;
    int tid = threadIdx.x, bid = blockIdx.x;
    int wid = tid >> 5, lane = tid & 31;

    for (int i = bid * 256 + tid; i < NN; i += NBI * 256) g_deg[i] = 0;
    for (int i = bid * 256 + tid; i < 3 * NSLOT * 128; i += NBI * 256)
        ((float*)g_bnacc)[i] = 0.0f;
    grid_barrier(NBI);

    for (int e = bid * 256 + tid; e < EE; e += NBI * 256)
        atomicAdd(&g_deg[ei[EE + e]], 1);
    grid_barrier(NBI);

    int base = bid * CH;
    {
        int psum = 0;
        for (int j = tid; j < CH; j += 256) {
            int n = base + j;
            if (n < NN) psum += g_deg[n];
        }
        #pragma unroll
        for (int off = 16; off > 0; off >>= 1) psum += __shfl_down_sync(FULLM, psum, off);
        if (lane == 0) s_w1[wid] = psum;
        __syncthreads();
        if (tid == 0) {
            int t = 0;
            #pragma unroll
            for (int w = 0; w < 8; w++) t += s_w1[w];
            g_bsum[bid] = t;
        }
    }
    grid_barrier(NBI);

    {
        int off = 0;
        for (int b = tid; b < NBI; b += 256)
            if (b < bid) off += g_bsum[b];
        #pragma unroll
        for (int o = 16; o > 0; o >>= 1) off += __shfl_down_sync(FULLM, off, o);
        if (lane == 0) s_w2[wid] = off;
        __syncthreads();
        if (tid == 0) {
            int t = 0;
            #pragma unroll
            for (int w = 0; w < 8; w++) t += s_w2[w];
            s_boff = t;
        }
        __syncthreads();
        int boff = s_boff;

        int n0 = base + 2 * tid, n1 = n0 + 1;
        int d0 = (2 * tid     < CH && n0 < NN) ? g_deg[n0] : 0;
        int d1 = (2 * tid + 1 < CH && n1 < NN) ? g_deg[n1] : 0;
        int pair = d0 + d1;
        int incl = pair;
        #pragma unroll
        for (int o = 1; o < 32; o <<= 1) {
            int v = __shfl_up_sync(FULLM, incl, o);
            if (lane >= o) incl += v;
        }
        __syncthreads();
        if (lane == 31) s_w1[wid] = incl;
        __syncthreads();
        int woff = 0;
        for (int w = 0; w < wid; w++) woff += s_w1[w];
        int excl = incl - pair + woff;
        int rs0 = boff + excl;
        int rs1 = rs0 + d0;
        if (2 * tid < CH && n0 <= NN) {
            g_rowstart[n0] = rs0;
            if (n0 < NN) g_cursor[n0] = rs0;
        }
        if (2 * tid + 1 < CH && n1 <= NN) {
            g_rowstart[n1] = rs1;
            if (n1 < NN) g_cursor[n1] = rs1;
        }
    }
    grid_barrier(NBI);

    for (int e = bid * 256 + tid; e < EE; e += NBI * 256) {
        int d = ei[EE + e];
        int s = ei[e];
        int p = atomicAdd(&g_cursor[d], 1);
        g_esrc[p] = s;
        g_epos[e] = p;
    }
}

// ---------------- input projection ----------------
__global__ void k_lin(const float* __restrict__ x,
                      const float* __restrict__ lin_w,
                      const float* __restrict__ lin_b) {
    __shared__ float ws[2048];
    __shared__ float xt[8 * 32];
    int c = threadIdx.x;
    int r = threadIdx.y;
    int tid = c + r * 64;
    for (int i = tid; i < 2048; i += 512) ws[i] = lin_w[i];
    if (tid < 256) {
        int rr = tid >> 5, kk = tid & 31;
        xt[rr * 32 + kk] = x[(blockIdx.x * 8 + rr) * 32 + kk];
    }
    __syncthreads();
    float a = lin_b[c];
    #pragma unroll
    for (int k = 0; k < 32; k++) a = fmaf(xt[r * 32 + k], ws[k * 64 + c], a);
    a = fmaxf(a, 0.0f);
    g_h[(blockIdx.x * 8 + r) * 64 + c] = a;
    __syncthreads();
    ws[r * 64 + c] = a;
    __syncthreads();
    if (r == 0) {
        float s1 = 0.f, s2 = 0.f;
        #pragma unroll
        for (int rr = 0; rr < 8; rr++) {
            float v = ws[rr * 64 + c];
            s1 += v; s2 += v * v;
        }
        int slot = blockIdx.x & (NSLOT - 1);
        atomicAdd(&g_bnacc[0][slot][c], s1);
        atomicAdd(&g_bnacc[0][slot][64 + c], s2);
    }
}

// ---------------- bn finalize ----------------
__global__ void k_bnfin(int l,
                        const float* __restrict__ gamma,
                        const float* __restrict__ beta,
                        const float* __restrict__ conv_w,
                        const float* __restrict__ conv_we,
                        const float* __restrict__ att_src,
                        const float* __restrict__ att_dst,
                        const float* __restrict__ att_edge) {
    int tid = threadIdx.x;
    if (tid < 64) {
        float s1 = 0.f, s2 = 0.f;
        for (int b = 0; b < NSLOT; b++) {
            s1 += g_bnacc[l][b][tid];
            s2 += g_bnacc[l][b][64 + tid];
        }
        float mu = s1 / (float)NN;
        float var = s2 / (float)NN - mu * mu;
        float sc = gamma[l * 64 + tid] * rsqrtf(var + 1e-5f);
        g_scale[tid] = sc;
        g_shift[tid] = beta[l * 64 + tid] - mu * sc;
    }
    if (tid < 4) g_gmaxu[tid] = encf(-1e30f);
    {
        int h = tid >> 6, k = tid & 63;
        const float* W = conv_w + l * 16384 + k * 256 + h * 64;
        const float* as = att_src + l * 256 + h * 64;
        const float* ad = att_dst + l * 256 + h * 64;
        float vs = 0.f, vd = 0.f;
        #pragma unroll 8
        for (int c = 0; c < 64; c++) { float w = W[c]; vs += w * as[c]; vd += w * ad[c]; }
        g_vsrc[tid] = vs;
        g_vdst[tid] = vd;
    }
    if (tid < 32) {
        int h = tid >> 3, j = tid & 7;
        const float* We = conv_we + l * 2048 + j * 256 + h * 64;
        const float* ae = att_edge + l * 256 + h * 64;
        float we = 0.f;
        #pragma unroll 8
        for (int c = 0; c < 64; c++) we += We[c] * ae[c];
        g_wedge[tid] = we;
    }
}

// ---------------- bn apply (R14 version) ----------------
__global__ __launch_bounds__(256, 4) void k_bnapply() {
    __shared__ float hn[64 * PAD];
    __shared__ float vv[8 * PAD];
    __shared__ float ssc[64], ssh[64];
    int tid = threadIdx.x;
    int nb = blockIdx.x * 64;

    if (tid < 64) { ssc[tid] = g_scale[tid]; ssh[tid] = g_shift[tid]; }
    for (int i = tid; i < 512; i += 256) {
        int j = i >> 6, c = i & 63;
        vv[j * PAD + c] = (j < 4) ? g_vsrc[j * 64 + c] : g_vdst[(j - 4) * 64 + c];
    }
    __syncthreads();

    #pragma unroll 1
    for (int i = tid * 4; i < 4096; i += 1024) {
        int node = i >> 6, c = i & 63;
        float4 hq = *(const float4*)&g_h[nb * 64 + i];
        float4 o;
        o.x = hq.x * ssc[c]     + ssh[c];
        o.y = hq.y * ssc[c + 1] + ssh[c + 1];
        o.z = hq.z * ssc[c + 2] + ssh[c + 2];
        o.w = hq.w * ssc[c + 3] + ssh[c + 3];
        __half2 h0 = __floats2half2_rn(o.x, o.y);
        __half2 h1 = __floats2half2_rn(o.z, o.w);
        *(__half2*)&g_hnh[nb * 64 + i]     = h0;
        *(__half2*)&g_hnh[nb * 64 + i + 2] = h1;
        *(float4*)&hn[node * PAD + c] = o;
    }
    __syncthreads();

    #pragma unroll 1
    for (int rep = 0; rep < 2; rep++) {
        int o = tid + rep * 256;
        int node = o >> 3, j = o & 7;
        const float* hrow = &hn[node * PAD];
        const float* vrow = &vv[j * PAD];
        float acc = 0.f;
        #pragma unroll 8
        for (int c4 = 0; c4 < 64; c4 += 4) {
            float4 hq = *(const float4*)&hrow[c4];
            float4 vq = *(const float4*)&vrow[c4];
            acc += hq.x * vq.x + hq.y * vq.y + hq.z * vq.z + hq.w * vq.w;
        }
        int n = nb + node;
        if (j < 4) g_as[n * 4 + j] = acc;
        else       g_ad[n * 4 + j - 4] = acc;
    }
}

// ---------------- edge scores ----------------
__global__ void k_escore(const float* __restrict__ edge_attr,
                         const int* __restrict__ ei) {
    __shared__ float we[32];
    __shared__ float red[8][4];
    int tid = threadIdx.x;
    if (tid < 32) we[tid] = g_wedge[tid];
    __syncthreads();
    int e = blockIdx.x * 256 + tid;
    float o[4] = {-1e30f, -1e30f, -1e30f, -1e30f};
    if (e < EE) {
        int sv = ei[e];
        int dv = ei[EE + e];
        float4 as4 = *(const float4*)&g_as[sv * 4];
        float4 ad4 = *(const float4*)&g_ad[dv * 4];
        float4 e0 = *(const float4*)(edge_attr + e * 8);
        float4 e1 = *(const float4*)(edge_attr + e * 8 + 4);
        float ax[4] = {as4.x + ad4.x, as4.y + ad4.y, as4.z + ad4.z, as4.w + ad4.w};
        #pragma unroll
        for (int h = 0; h < 4; h++) {
            const float* w = &we[h * 8];
            float ae = e0.x*w[0] + e0.y*w[1] + e0.z*w[2] + e0.w*w[3]
                     + e1.x*w[4] + e1.y*w[5] + e1.z*w[6] + e1.w*w[7];
            o[h] = lrelu(ax[h] + ae);
        }
        int p = g_epos[e];
        *(float4*)&g_sc[p * 4] = make_float4(o[0], o[1], o[2], o[3]);
    }
    float m[4] = {o[0], o[1], o[2], o[3]};
    #pragma unroll
    for (int off = 16; off > 0; off >>= 1) {
        #pragma unroll
        for (int h = 0; h < 4; h++)
            m[h] = fmaxf(m[h], __shfl_xor_sync(FULLM, m[h], off));
    }
    if ((tid & 31) == 0) {
        #pragma unroll
        for (int h = 0; h < 4; h++) red[tid >> 5][h] = m[h];
    }
    __syncthreads();
    if (tid < 4) {
        float mm = red[0][tid];
        #pragma unroll
        for (int wg = 1; wg < 8; wg++) mm = fmaxf(mm, red[wg][tid]);
        atomicMax(&g_gmaxu[tid], encf(mm));
    }
}

// ---------------- conv: softmax-agg -> HMMA (mma.sync) GEMM -> epilogue ----
// 256 threads, 32 nodes/block. sA: s[32][SPADH] fp16; sBT: W^T[64][SPADH] fp16.
// 8 warps: (mtile in {0,1}) x (2 n8-tiles); mma.m16n8k16 f16->f32.
__global__ __launch_bounds__(256, 4) void k_conv_gemm(
        int l,
        const float* __restrict__ conv_w,
        const float* __restrict__ conv_bias) {
    extern __shared__ char smc[];
    __half* sA  = (__half*)smc;                   // 32 x SPADH halves
    __half* sBT = (__half*)(smc + 32 * SPADH * 2); // 64 x SPADH halves
    float*  stats = (float*)smc;                  // reused after mma (132 stride)
    __shared__ float sbias[64];
    int tid = threadIdx.x;
    int wid = tid >> 5, lane = tid & 31;
    int nb = blockIdx.x * 32;

    if (tid < 64) sbias[tid] = conv_bias[l * 64 + tid];

    // stage B = W^T fp16 (coalesced global reads)
    {
        const float* Wg = conv_w + l * 16384;
        for (int i = tid; i < 16384; i += 256) {
            int c = i & 63, K = i >> 6;
            sBT[c * SPADH + K] =
                __float2half_rn(Wg[(K & 63) * 256 + (K >> 6) * 64 + c]);
        }
    }

    // ---------- Phase A: single-pass softmax + aggregation -> sA fp16 -----
    float gm0 = decf(g_gmaxu[0]);
    float gm1 = decf(g_gmaxu[1]);
    float gm2 = decf(g_gmaxu[2]);
    float gm3 = decf(g_gmaxu[3]);
    for (int jj = 0; jj < 4; jj++) {
        int nloc = (wid << 2) + jj;
        int n = nb + nloc;
        int start = g_rowstart[n];
        int end   = g_rowstart[n + 1];
        float den0 = 0.f, den1 = 0.f, den2 = 0.f, den3 = 0.f;
        float aA0 = 0.f, aA1 = 0.f, aA2 = 0.f, aA3 = 0.f;
        float aB0 = 0.f, aB1 = 0.f, aB2 = 0.f, aB3 = 0.f;
        for (int i = start; i < end; i++) {
            float4 sc = *(const float4*)&g_sc[i * 4];
            int sv = g_esrc[i];
            float w0 = __expf(sc.x - gm0);
            float w1 = __expf(sc.y - gm1);
            float w2 = __expf(sc.z - gm2);
            float w3 = __expf(sc.w - gm3);
            den0 += w0; den1 += w1; den2 += w2; den3 += w3;
            __half2 hh = ((const __half2*)g_hnh)[sv * 32 + lane];
            float2 hf = __half22float2(hh);
            aA0 = fmaf(w0, hf.x, aA0); aB0 = fmaf(w0, hf.y, aB0);
            aA1 = fmaf(w1, hf.x, aA1); aB1 = fmaf(w1, hf.y, aB1);
            aA2 = fmaf(w2, hf.x, aA2); aB2 = fmaf(w2, hf.y, aB2);
            aA3 = fmaf(w3, hf.x, aA3); aB3 = fmaf(w3, hf.y, aB3);
        }
        float i0 = 1.f / (den0 + 1e-16f);
        float i1 = 1.f / (den1 + 1e-16f);
        float i2 = 1.f / (den2 + 1e-16f);
        float i3 = 1.f / (den3 + 1e-16f);
        __half* arow = sA + nloc * SPADH;
        *(__half2*)&arow[  0 + 2 * lane] = __floats2half2_rn(aA0 * i0, aB0 * i0);
        *(__half2*)&arow[ 64 + 2 * lane] = __floats2half2_rn(aA1 * i1, aB1 * i1);
        *(__half2*)&arow[128 + 2 * lane] = __floats2half2_rn(aA2 * i2, aB2 * i2);
        *(__half2*)&arow[192 + 2 * lane] = __floats2half2_rn(aA3 * i3, aB3 * i3);
    }
    __syncthreads();

    // ---------- Phase B: HMMA GEMM [32 x 256] @ [256 x 64] ----------
    int mtile = wid & 1;          // 16-node tile
    int nt0   = (wid >> 1) * 2;   // first of two n8 tiles
    float c0[4] = {0.f, 0.f, 0.f, 0.f};
    float c1[4] = {0.f, 0.f, 0.f, 0.f};
    unsigned baseA = smem_u32(sA);
    unsigned baseB = smem_u32(sBT);
    int arow_idx = mtile * 16 + (lane & 15);
    int acol_off = (lane >> 4) * 8;
    int brow0 = (nt0 + 0) * 8 + (lane & 7);
    int brow1 = (nt0 + 1) * 8 + (lane & 7);
    int bcol_off = ((lane >> 3) & 1) * 8;
    #pragma unroll
    for (int kt = 0; kt < 16; kt++) {
        int kb = kt * 16;
        unsigned a0, a1, a2, a3, b0, b1;
        unsigned addrA = baseA + (unsigned)(arow_idx * SPADH + kb + acol_off) * 2u;
        asm volatile("ldmatrix.sync.aligned.m8n8.x4.shared.b16 {%0,%1,%2,%3}, [%4];"
                     : "=r"(a0), "=r"(a1), "=r"(a2), "=r"(a3) : "r"(addrA));
        unsigned addrB0 = baseB + (unsigned)(brow0 * SPADH + kb + bcol_off) * 2u;
        asm volatile("ldmatrix.sync.aligned.m8n8.x2.shared.b16 {%0,%1}, [%2];"
                     : "=r"(b0), "=r"(b1) : "r"(addrB0));
        asm volatile("mma.sync.aligned.m16n8k16.row.col.f32.f16.f16.f32 "
                     "{%0,%1,%2,%3}, {%4,%5,%6,%7}, {%8,%9}, {%0,%1,%2,%3};"
                     : "+f"(c0[0]), "+f"(c0[1]), "+f"(c0[2]), "+f"(c0[3])
                     : "r"(a0), "r"(a1), "r"(a2), "r"(a3), "r"(b0), "r"(b1));
        unsigned addrB1 = baseB + (unsigned)(brow1 * SPADH + kb + bcol_off) * 2u;
        asm volatile("ldmatrix.sync.aligned.m8n8.x2.shared.b16 {%0,%1}, [%2];"
                     : "=r"(b0), "=r"(b1) : "r"(addrB1));
        asm volatile("mma.sync.aligned.m16n8k16.row.col.f32.f16.f16.f32 "
                     "{%0,%1,%2,%3}, {%4,%5,%6,%7}, {%8,%9}, {%0,%1,%2,%3};"
                     : "+f"(c1[0]), "+f"(c1[1]), "+f"(c1[2]), "+f"(c1[3])
                     : "r"(a0), "r"(a1), "r"(a2), "r"(a3), "r"(b0), "r"(b1));
    }
    __syncthreads();   // sA/sBT reads complete; stats region reusable

    // ---------- epilogue: mean/bias/relu/skip + BN stats ----------
    int r0 = lane >> 2;
    int cpair = 2 * (lane & 3);
    #pragma unroll
    for (int t = 0; t < 2; t++) {
        float* cc = t ? c1 : c0;
        int cb = (nt0 + t) * 8 + cpair;
        #pragma unroll
        for (int hv = 0; hv < 2; hv++) {
            int nl = mtile * 16 + r0 + hv * 8;
            int node = nb + nl;
            float vx = cc[hv * 2 + 0], vy = cc[hv * 2 + 1];
            float2 old = *(const float2*)&g_h[node * 64 + cb];
            float ox = fmaxf(vx * 0.25f + sbias[cb],     0.f) + old.x;
            float oy = fmaxf(vy * 0.25f + sbias[cb + 1], 0.f) + old.y;
            *(float2*)&g_h[node * 64 + cb] = make_float2(ox, oy);
            if (l < 2) {
                stats[nl * 132 + cb]          = ox;
                stats[nl * 132 + cb + 1]      = oy;
                stats[nl * 132 + 64 + cb]     = ox * ox;
                stats[nl * 132 + 64 + cb + 1] = oy * oy;
            }
        }
    }
    if (l < 2) {
        __syncthreads();
        if (tid < 128) {
            float acc = 0.f;
            #pragma unroll 8
            for (int q = 0; q < 32; q++) acc += stats[q * 132 + tid];
            atomicAdd(&g_bnacc[l + 1][blockIdx.x & (NSLOT - 1)][tid], acc);
        }
    }
}

// ---------------- pooling + MLP head ----------------
__device__ __forceinline__ int lower_bound_dev(const int* b, int n, int v) {
    int lo = 0, hi = n;
    while (lo < hi) {
        int mid = (lo + hi) >> 1;
        if (b[mid] < v) lo = mid + 1; else hi = mid;
    }
    return lo;
}

__global__ void k_pool_mlp(const int* __restrict__ batch,
                           const float* __restrict__ fc1_w,
                           const float* __restrict__ fc1_b,
                           const float* __restrict__ fc2_w,
                           const float* __restrict__ fc2_b,
                           float* __restrict__ out) {
    __shared__ float ps[64];
    __shared__ float r2[2];
    int g = blockIdx.x;
    int tid = threadIdx.x;
    int start = lower_bound_dev(batch, NN, g);
    int end   = lower_bound_dev(batch, NN, g + 1);
    float s = 0.f;
    for (int n = start; n < end; n++) s += g_h[n * 64 + tid];
    ps[tid] = s;
    __syncthreads();
    float z = fc1_b[tid];
    #pragma unroll 8
    for (int k = 0; k < 64; k++) z = fmaf(ps[k], fc1_w[k * 64 + tid], z);
    z = fmaxf(z, 0.0f);
    float p = z * fc2_w[tid];
    #pragma unroll
    for (int off = 16; off > 0; off >>= 1) p += __shfl_down_sync(FULLM, p, off);
    if ((tid & 31) == 0) r2[tid >> 5] = p;
    __syncthreads();
    if (tid == 0) out[g] = fmaxf(r2[0] + r2[1] + fc2_b[0], 0.0f);
}

// ---------------- launcher ----------------
extern "C" void kernel_launch(void* const* d_in, const int* in_sizes, int n_in,
                              void* d_out, int out_size) {
    const float* x         = (const float*)d_in[0];
    const int*   ei        = (const int*)  d_in[1];
    const float* edge_attr = (const float*)d_in[2];
    const int*   batch     = (const int*)  d_in[3];
    const float* lin_w     = (const float*)d_in[4];
    const float* lin_b     = (const float*)d_in[5];
    const float* bn_gamma  = (const float*)d_in[6];
    const float* bn_beta   = (const float*)d_in[7];
    const float* conv_w    = (const float*)d_in[8];
    const float* conv_we   = (const float*)d_in[9];
    const float* att_src   = (const float*)d_in[10];
    const float* att_dst   = (const float*)d_in[11];
    const float* att_edge  = (const float*)d_in[12];
    const float* conv_bias = (const float*)d_in[13];
    const float* fc1_w     = (const float*)d_in[14];
    const float* fc1_b     = (const float*)d_in[15];
    const float* fc2_w     = (const float*)d_in[16];
    const float* fc2_b     = (const float*)d_in[17];
    float* out = (float*)d_out;

    cudaFuncSetAttribute(k_conv_gemm, cudaFuncAttributeMaxDynamicSharedMemorySize,
                         SMEM_CONV);

    k_csr<<<NBI, 256>>>(ei);
    k_lin<<<NN / 8, dim3(64, 8)>>>(x, lin_w, lin_b);

    for (int l = 0; l < 3; l++) {
        k_bnfin<<<1, 256>>>(l, bn_gamma, bn_beta, conv_w, conv_we,
                            att_src, att_dst, att_edge);
        k_bnapply<<<NN / 64, 256>>>();
        k_escore<<<(EE + 255) / 256, 256>>>(edge_attr, ei);
        k_conv_gemm<<<NN / 32, 256, SMEM_CONV>>>(l, conv_w, conv_bias);
    }

    k_pool_mlp<<<GG, 64>>>(batch, fc1_w, fc1_b, fc2_w, fc2_b, out);
}